// round 10
// baseline (speedup 1.0000x reference)
#include <cuda_runtime.h>
#include <cstdint>
#include <mma.h>

using namespace nvcuda;

#define DMODEL 1024
#define NH     16
#define DH     64
#define BATCH  4
#define SEQ    1024
#define JT     32            // j chunk
#define NC     (SEQ/JT)      // 32 chunks
#define IT2    2             // i per CTA

// Scratch (static device globals)
__device__ float g_q  [(size_t)BATCH*SEQ*DMODEL];   // [b, i, h*64+d]
__device__ float g_k  [(size_t)BATCH*SEQ*DH];       // [b, j, d]
__device__ float g_v  [(size_t)BATCH*SEQ*DH];       // [b, j, d]
__device__ float g_ctx[(size_t)BATCH*SEQ*DMODEL];   // [b, i, h*64+d]

// ---------------------------------------------------------------------------
__device__ __forceinline__ void cp16(void* dst, const void* src) {
    unsigned d = (unsigned)__cvta_generic_to_shared(dst);
    asm volatile("cp.async.cg.shared.global [%0], [%1], 16;" :: "r"(d), "l"(src));
}
__device__ __forceinline__ void cp_commit() { asm volatile("cp.async.commit_group;"); }
template<int N> __device__ __forceinline__ void cp_wait() {
    asm volatile("cp.async.wait_group %0;" :: "n"(N));
}
template<class F> __device__ __forceinline__ void to_tf32(F& f) {
    #pragma unroll
    for (int t = 0; t < f.num_elements; ++t)
        f.x[t] = wmma::__float_to_tf32(f.x[t]);
}

// ===========================================================================
// Fused attention: CTA = 2 i values, 512 threads (16 warps), j-loop of 32
// chunks, double-buffered cp.async staging.  P never touches gmem.
//   S[r, j] = q·k + q·rel   (r = il*64 + b*16 + h, 128 rows x 32 j)
//   P = exp(S/8);  lsum[r] += rowsum;  O[r, d] += P·V
//   ctx = O / lsum
// NOTE: all cp.async/float4-addressed rows use 68-float padding (272 B = 17*16,
// keeps 16-byte alignment).  Ps uses 36 (144 B).
// ===========================================================================
struct FBuf  { float R[IT2][JT][68]; float K[4][JT][68]; float V[4][JT][68]; };
struct FSmem {
    float Qs[IT2][64][68];
    FBuf  buf[2];
    float Ps[128][36];
    float lsum[128];
};
#define FUSED_SMEM ((int)sizeof(FSmem))

__global__ void __launch_bounds__(512, 1)
fused_attn_kernel(const float* __restrict__ rel)
{
    extern __shared__ float smraw[];
    FSmem* sm = reinterpret_cast<FSmem*>(smraw);

    const int tid  = threadIdx.x;
    const int warp = tid >> 5;
    const int rb   = warp >> 1;          // 16-row block: il = rb>>2, b = rb&3
    const int wil  = rb >> 2;
    const int wb   = rb & 3;
    const int wh   = warp & 1;           // j-half (S phase) / d-half (AV phase)
    const int i0   = blockIdx.x * IT2;

    // ---- staging helper for one j chunk into buf[pb]
    auto stage = [&](int pb, int j0) {
        FBuf& B = sm->buf[pb];
        #pragma unroll
        for (int t = 0; t < 2; ++t) {                 // rel: 1024 float4
            int idx = tid + t*512;
            int il  = idx >> 9;
            int j   = (idx >> 4) & 31;
            int c4  = (idx & 15) * 4;
            cp16(&B.R[il][j][c4],
                 rel + ((size_t)(i0 + il)*SEQ + j0 + j)*DH + c4);
        }
        #pragma unroll
        for (int t = 0; t < 4; ++t) {                 // K: 2048 float4
            int idx = tid + t*512;
            int b   = idx >> 9;
            int j   = (idx >> 4) & 31;
            int c4  = (idx & 15) * 4;
            cp16(&B.K[b][j][c4], g_k + ((size_t)b*SEQ + j0 + j)*DH + c4);
        }
        #pragma unroll
        for (int t = 0; t < 4; ++t) {                 // V: 2048 float4
            int idx = tid + t*512;
            int b   = idx >> 9;
            int j   = (idx >> 4) & 31;
            int c4  = (idx & 15) * 4;
            cp16(&B.V[b][j][c4], g_v + ((size_t)b*SEQ + j0 + j)*DH + c4);
        }
        cp_commit();
    };

    // ---- prologue: Q rows (both i), lsum zero, first chunk
    #pragma unroll
    for (int t = 0; t < 4; ++t) {                     // Q: 2048 float4
        int idx = tid + t*512;
        int il  = idx >> 10;
        int r   = (idx >> 4) & 63;
        int c4  = (idx & 15) * 4;
        int b = r >> 4, h = r & 15;
        cp16(&sm->Qs[il][r][c4],
             g_q + ((size_t)(b*SEQ + i0 + il))*DMODEL + h*DH + c4);
    }
    if (tid < 128) sm->lsum[tid] = 0.0f;
    stage(0, 0);

    // O accumulator: warp owns rows [rb*16, +16), cols [wh*32, +32)
    wmma::fragment<wmma::accumulator, 16, 16, 8, float> of[2];
    wmma::fill_fragment(of[0], 0.0f);
    wmma::fill_fragment(of[1], 0.0f);

    for (int c = 0; c < NC; ++c) {
        const int pb = c & 1;
        cp_wait<0>();
        __syncthreads();                  // buf[pb] ready; prev AV complete

        if (c + 1 < NC) stage(pb ^ 1, (c + 1)*JT);

        FBuf& B = sm->buf[pb];

        // ---- S = Q·K^T + Q·R^T  (warp: 16 rows x 16 j)
        wmma::fragment<wmma::accumulator, 16, 16, 8, float> sf;
        wmma::fill_fragment(sf, 0.0f);
        #pragma unroll
        for (int kf = 0; kf < 8; ++kf) {
            wmma::fragment<wmma::matrix_a, 16, 16, 8, wmma::precision::tf32, wmma::row_major> af;
            wmma::fragment<wmma::matrix_b, 16, 16, 8, wmma::precision::tf32, wmma::col_major> bk, br;
            wmma::load_matrix_sync(af, &sm->Qs[wil][wb*16][kf*8], 68);
            to_tf32(af);
            wmma::load_matrix_sync(bk, &B.K[wb][wh*16][kf*8], 68);
            to_tf32(bk);
            wmma::mma_sync(sf, af, bk, sf);
            wmma::load_matrix_sync(br, &B.R[wil][wh*16][kf*8], 68);
            to_tf32(br);
            wmma::mma_sync(sf, af, br, sf);
        }
        #pragma unroll
        for (int t = 0; t < sf.num_elements; ++t)
            sf.x[t] = __expf(sf.x[t] * 0.125f);
        wmma::store_matrix_sync(&sm->Ps[rb*16][wh*16], sf, 36, wmma::mem_row_major);
        __syncthreads();                  // Ps complete

        // ---- row sums (4 threads/row, 8 cols each)
        {
            int r = tid >> 2;
            int q = tid & 3;
            float s = 0.0f;
            #pragma unroll
            for (int cc = 0; cc < 8; ++cc) s += sm->Ps[r][q*8 + cc];
            s += __shfl_xor_sync(0xffffffffu, s, 1);
            s += __shfl_xor_sync(0xffffffffu, s, 2);
            if (q == 0) sm->lsum[r] += s;
        }

        // ---- O += P · V   (warp: 16 rows x 32 d)
        #pragma unroll
        for (int kf = 0; kf < 4; ++kf) {
            wmma::fragment<wmma::matrix_a, 16, 16, 8, wmma::precision::tf32, wmma::row_major> af;
            wmma::load_matrix_sync(af, &sm->Ps[rb*16][kf*8], 36);
            to_tf32(af);
            #pragma unroll
            for (int nf = 0; nf < 2; ++nf) {
                wmma::fragment<wmma::matrix_b, 16, 16, 8, wmma::precision::tf32, wmma::row_major> bf;
                wmma::load_matrix_sync(bf, &B.V[wb][kf*8][wh*32 + nf*16], 68);
                to_tf32(bf);
                wmma::mma_sync(of[nf], af, bf, of[nf]);
            }
        }
    }

    // ---- epilogue: stage O into smem (reuse buf[0]), divide by lsum, write
    __syncthreads();
    float (*Os)[68] = reinterpret_cast<float (*)[68]>(&sm->buf[0].R[0][0][0]);
    #pragma unroll
    for (int nf = 0; nf < 2; ++nf)
        wmma::store_matrix_sync(&Os[rb*16][wh*32 + nf*16], of[nf], 68,
                                wmma::mem_row_major);
    __syncthreads();

    #pragma unroll
    for (int t = 0; t < 4; ++t) {                     // 2048 float4
        int idx = tid + t*512;
        int r   = idx >> 4;            // 0..127
        int c4  = (idx & 15) * 4;
        int il  = r >> 6;
        int rr  = r & 63;
        int b = rr >> 4, h = rr & 15;
        float inv = 1.0f / sm->lsum[r];
        float4 o;
        o.x = Os[r][c4+0] * inv;
        o.y = Os[r][c4+1] * inv;
        o.z = Os[r][c4+2] * inv;
        o.w = Os[r][c4+3] * inv;
        *reinterpret_cast<float4*>(
            g_ctx + ((size_t)(b*SEQ + i0 + il))*DMODEL + h*DH + c4) = o;
    }
}

// ===========================================================================
// 128x128 NT GEMM (C = A·B^T), cp.async double-buffered, 8 warps (warp 32x64)
// ===========================================================================
struct ProjSmem { float A[2][128][36]; float B[2][128][36]; };
#define PROJ_SMEM ((int)sizeof(ProjSmem))

__global__ void __launch_bounds__(256, 2)
gemm_nt_128p(const float* __restrict__ A, int lda,
             const float* __restrict__ B, int ldb,
             float* __restrict__ C, int ldc, int K)
{
    extern __shared__ float smraw[];
    ProjSmem* sm = reinterpret_cast<ProjSmem*>(smraw);

    const int tid  = threadIdx.x;
    const int warp = tid >> 5;
    const int wm   = warp >> 1;      // 0..3
    const int wn   = warp & 1;       // 0..1

    A += (size_t)blockIdx.x * 128 * lda;
    B += (size_t)blockIdx.y * 128 * ldb;
    C += (size_t)blockIdx.x * 128 * ldc + (size_t)blockIdx.y * 128;

    auto stage = [&](int buf, int k0) {
        #pragma unroll
        for (int t = 0; t < 4; ++t) {
            int idx = tid + t*256;           // 0..1023
            int r   = idx >> 3;              // 0..127
            int c4  = (idx & 7) * 4;         // 0..28
            cp16(&sm->A[buf][r][c4], A + (size_t)r*lda + k0 + c4);
            cp16(&sm->B[buf][r][c4], B + (size_t)r*ldb + k0 + c4);
        }
        cp_commit();
    };

    wmma::fragment<wmma::accumulator, 16, 16, 8, float> cf[2][4];
    #pragma unroll
    for (int mi = 0; mi < 2; ++mi)
        #pragma unroll
        for (int ni = 0; ni < 4; ++ni) wmma::fill_fragment(cf[mi][ni], 0.0f);

    stage(0, 0);
    int cur = 0;
    for (int k0 = 0; k0 < K; k0 += 32) {
        if (k0 + 32 < K) { stage(cur ^ 1, k0 + 32); cp_wait<1>(); }
        else             { cp_wait<0>(); }
        __syncthreads();

        #pragma unroll
        for (int kf = 0; kf < 4; ++kf) {
            wmma::fragment<wmma::matrix_a, 16, 16, 8, wmma::precision::tf32, wmma::row_major> af[2];
            wmma::fragment<wmma::matrix_b, 16, 16, 8, wmma::precision::tf32, wmma::col_major> bf[4];
            #pragma unroll
            for (int mi = 0; mi < 2; ++mi) {
                wmma::load_matrix_sync(af[mi], &sm->A[cur][wm*32 + mi*16][kf*8], 36);
                to_tf32(af[mi]);
            }
            #pragma unroll
            for (int ni = 0; ni < 4; ++ni) {
                wmma::load_matrix_sync(bf[ni], &sm->B[cur][wn*64 + ni*16][kf*8], 36);
                to_tf32(bf[ni]);
            }
            #pragma unroll
            for (int mi = 0; mi < 2; ++mi)
                #pragma unroll
                for (int ni = 0; ni < 4; ++ni)
                    wmma::mma_sync(cf[mi][ni], af[mi], bf[ni], cf[mi][ni]);
        }
        __syncthreads();
        cur ^= 1;
    }

    #pragma unroll
    for (int mi = 0; mi < 2; ++mi)
        #pragma unroll
        for (int ni = 0; ni < 4; ++ni)
            wmma::store_matrix_sync(
                C + (size_t)(wm*32 + mi*16)*ldc + (wn*64 + ni*16),
                cf[mi][ni], ldc, wmma::mem_row_major);
}

// ===========================================================================
// 64x64-tile NT GEMM for the narrow K/V projections (N = 64)
// ===========================================================================
__global__ void gemm_nt_64k(const float* __restrict__ A, int lda,
                            const float* __restrict__ B, int ldb,
                            float* __restrict__ C, int ldc, int K)
{
    __shared__ float As[64][36];
    __shared__ float Bs[64][36];
    const int tid  = threadIdx.x;
    const int warp = tid >> 5;
    const int wm   = warp >> 1;
    const int wn   = warp & 1;

    A += (size_t)blockIdx.x * 64 * lda;
    C += (size_t)blockIdx.x * 64 * ldc;

    wmma::fragment<wmma::accumulator, 16, 16, 8, float> cf[2][2];
    #pragma unroll
    for (int mi = 0; mi < 2; ++mi)
        #pragma unroll
        for (int ni = 0; ni < 2; ++ni) wmma::fill_fragment(cf[mi][ni], 0.0f);

    for (int k0 = 0; k0 < K; k0 += 32) {
        #pragma unroll
        for (int it = 0; it < 4; ++it) {
            int s = tid + it*128;
            int r = s >> 3;
            int c = (s & 7) * 4;
            float4 va = *reinterpret_cast<const float4*>(A + (size_t)r*lda + k0 + c);
            As[r][c+0] = wmma::__float_to_tf32(va.x);
            As[r][c+1] = wmma::__float_to_tf32(va.y);
            As[r][c+2] = wmma::__float_to_tf32(va.z);
            As[r][c+3] = wmma::__float_to_tf32(va.w);
            float4 vb = *reinterpret_cast<const float4*>(B + (size_t)r*ldb + k0 + c);
            Bs[r][c+0] = wmma::__float_to_tf32(vb.x);
            Bs[r][c+1] = wmma::__float_to_tf32(vb.y);
            Bs[r][c+2] = wmma::__float_to_tf32(vb.z);
            Bs[r][c+3] = wmma::__float_to_tf32(vb.w);
        }
        __syncthreads();

        #pragma unroll
        for (int kf = 0; kf < 4; ++kf) {
            wmma::fragment<wmma::matrix_a, 16, 16, 8, wmma::precision::tf32, wmma::row_major> af[2];
            wmma::fragment<wmma::matrix_b, 16, 16, 8, wmma::precision::tf32, wmma::col_major> bf[2];
            #pragma unroll
            for (int mi = 0; mi < 2; ++mi)
                wmma::load_matrix_sync(af[mi], &As[wm*32 + mi*16][kf*8], 36);
            #pragma unroll
            for (int ni = 0; ni < 2; ++ni)
                wmma::load_matrix_sync(bf[ni], &Bs[wn*32 + ni*16][kf*8], 36);
            #pragma unroll
            for (int mi = 0; mi < 2; ++mi)
                #pragma unroll
                for (int ni = 0; ni < 2; ++ni)
                    wmma::mma_sync(cf[mi][ni], af[mi], bf[ni], cf[mi][ni]);
        }
        __syncthreads();
    }

    #pragma unroll
    for (int mi = 0; mi < 2; ++mi)
        #pragma unroll
        for (int ni = 0; ni < 2; ++ni)
            wmma::store_matrix_sync(
                C + (size_t)(wm*32 + mi*16)*ldc + (wn*32 + ni*16),
                cf[mi][ni], ldc, wmma::mem_row_major);
}

// ---------------------------------------------------------------------------
__global__ void bias_add(float* __restrict__ out, const float* __restrict__ bo)
{
    size_t idx = (size_t)blockIdx.x * 256 + threadIdx.x;
    out[idx] += bo[idx & (DMODEL - 1)];
}

// ---------------------------------------------------------------------------
extern "C" void kernel_launch(void* const* d_in, const int* in_sizes, int n_in,
                              void* d_out, int out_size)
{
    const float* x   = (const float*)d_in[0];
    const float* rel = (const float*)d_in[1];
    const float* Wq  = (const float*)d_in[2];
    const float* Wk  = (const float*)d_in[3];
    const float* Wv  = (const float*)d_in[4];
    const float* Wo  = (const float*)d_in[5];
    const float* bo  = (const float*)d_in[6];
    float* out = (float*)d_out;

    float *q, *k, *v, *ctx;
    cudaGetSymbolAddress((void**)&q,   g_q);
    cudaGetSymbolAddress((void**)&k,   g_k);
    cudaGetSymbolAddress((void**)&v,   g_v);
    cudaGetSymbolAddress((void**)&ctx, g_ctx);

    cudaFuncSetAttribute(gemm_nt_128p, cudaFuncAttributeMaxDynamicSharedMemorySize, PROJ_SMEM);
    cudaFuncSetAttribute(fused_attn_kernel, cudaFuncAttributeMaxDynamicSharedMemorySize, FUSED_SMEM);

    // Projections: y = x @ W^T
    gemm_nt_128p<<<dim3(32, 8), 256, PROJ_SMEM>>>(x, DMODEL, Wq, DMODEL, q, DMODEL, DMODEL);
    gemm_nt_64k<<<dim3(64, 1), 128>>>(x, DMODEL, Wk, DMODEL, k, DH, DMODEL);
    gemm_nt_64k<<<dim3(64, 1), 128>>>(x, DMODEL, Wv, DMODEL, v, DH, DMODEL);

    // Fused c2c + c2p + softmax + AV (P never hits gmem)
    fused_attn_kernel<<<SEQ/IT2, 512, FUSED_SMEM>>>(rel);

    // out = ctx @ Wo^T + bo
    gemm_nt_128p<<<dim3(32, 8), 256, PROJ_SMEM>>>(ctx, DMODEL, Wo, DMODEL, out, DMODEL, DMODEL);
    bias_add<<<16384, 256>>>(out, bo);
}